// round 1
// baseline (speedup 1.0000x reference)
#include <cuda_runtime.h>
#include <cstddef>

#define NB   16
#define HH   512
#define WWID 512
#define NPB  20000
#define NPTS (NB * NPB)        // 320000
#define EPSV 1e-5f
#define NBLK 1250              // NPTS / 256 exactly

// ---------------- scratch (device globals; no allocation allowed) ----------------
__device__ int g_map[NB * HH * WWID];                       // 16.8 MB dense index map
__device__ __align__(16) float g_y1[NPTS * 8];              // conv1 out (pre-BN)
__device__ __align__(16) float g_y2[NPTS * 16];             // conv2 out (pre-BN)
__device__ __align__(16) float g_y3[NPTS * 32];             // conv3 out (pre-BN)
__device__ float g_part[NBLK * 64];                         // per-block [sum|sumsq] partials
__device__ float g_bn[64];                                  // current layer: a[0..31], b[32..63]
__device__ unsigned g_pool[NB * 32];                        // segment max (uint bits of relu'd f32)

// ---------------- init: map = -1, pool = 0 ----------------
__global__ void k_init() {
    int i = blockIdx.x * blockDim.x + threadIdx.x;
    int stride = gridDim.x * blockDim.x;
    for (int t = i; t < NB * HH * WWID; t += stride) g_map[t] = -1;
    if (i < NB * 32) g_pool[i] = 0u;
}

// ---------------- scatter point index into dense map ----------------
__global__ void k_scatter(const int* __restrict__ idx) {
    int i = blockIdx.x * blockDim.x + threadIdx.x;
    if (i < NPTS) {
        int b = idx[3 * i], y = idx[3 * i + 1], x = idx[3 * i + 2];
        g_map[(b << 18) | (y << 9) | x] = i;
    }
}

// ---------------- submanifold conv + fused input-BN-ReLU + stats partials ----------------
// in:  [NPTS, CIN] pre-BN features of previous layer (BN folded via g_bn if BN=true)
// out: [NPTS, COUT] pre-BN conv outputs
// Also emits per-block sum/sumsq of outputs into g_part (deterministic two-stage reduce).
template <int CIN, int COUT, bool BN>
__global__ __launch_bounds__(256)
void k_conv(const float* __restrict__ in, const int* __restrict__ idx,
            const float* __restrict__ w, float* __restrict__ out)
{
    __shared__ float ws[9 * CIN * COUT];
    __shared__ float s_ab[BN ? 2 * CIN : 2];
    for (int t = threadIdx.x; t < 9 * CIN * COUT; t += 256) ws[t] = w[t];
    if (BN) {
        for (int t = threadIdx.x; t < 2 * CIN; t += 256)
            s_ab[t] = (t < CIN) ? g_bn[t] : g_bn[32 + (t - CIN)];
    }
    __syncthreads();

    int i = blockIdx.x * 256 + threadIdx.x;      // grid is exact: NBLK*256 == NPTS
    float acc[COUT];
#pragma unroll
    for (int c = 0; c < COUT; c++) acc[c] = 0.f;

    int b = idx[3 * i], y = idx[3 * i + 1], x = idx[3 * i + 2];
    int base = b << 18;

#pragma unroll 1
    for (int ky = 0; ky < 3; ky++) {
        int ny = y + ky - 1;
        if ((unsigned)ny >= (unsigned)HH) continue;
#pragma unroll 1
        for (int kx = 0; kx < 3; kx++) {
            int nx = x + kx - 1;
            if ((unsigned)nx >= (unsigned)WWID) continue;
            int j = g_map[base + (ny << 9) + nx];
            if (j < 0) continue;
            const float* wr = &ws[(ky * 3 + kx) * (CIN * COUT)];
            const float* inr = in + (size_t)j * CIN;
            if (CIN >= 4) {
#pragma unroll
                for (int c4 = 0; c4 < CIN / 4; c4++) {
                    float4 v4 = reinterpret_cast<const float4*>(inr)[c4];
                    float vv[4] = {v4.x, v4.y, v4.z, v4.w};
#pragma unroll
                    for (int u = 0; u < 4; u++) {
                        int ci = c4 * 4 + u;
                        float v = vv[u];
                        if (BN) v = fmaxf(fmaf(v, s_ab[ci], s_ab[CIN + ci]), 0.f);
#pragma unroll
                        for (int co = 0; co < COUT; co++)
                            acc[co] = fmaf(v, wr[ci * COUT + co], acc[co]);
                    }
                }
            } else {
                float v = inr[0];
                if (BN) v = fmaxf(fmaf(v, s_ab[0], s_ab[CIN]), 0.f);
#pragma unroll
                for (int co = 0; co < COUT; co++)
                    acc[co] = fmaf(v, wr[co], acc[co]);
            }
        }
    }

    // vectorized store of pre-BN outputs
    float4* orow = reinterpret_cast<float4*>(out + (size_t)i * COUT);
#pragma unroll
    for (int c4 = 0; c4 < COUT / 4; c4++) {
        float4 o;
        o.x = acc[4 * c4 + 0]; o.y = acc[4 * c4 + 1];
        o.z = acc[4 * c4 + 2]; o.w = acc[4 * c4 + 3];
        orow[c4] = o;
    }

    // block-level sum/sumsq partials (deterministic; no atomics)
    int lane = threadIdx.x & 31, wid = threadIdx.x >> 5;
    __shared__ float red[8][64];
#pragma unroll
    for (int co = 0; co < COUT; co++) {
        float s = acc[co];
        float q = acc[co] * acc[co];
#pragma unroll
        for (int off = 16; off; off >>= 1) {
            s += __shfl_down_sync(0xffffffffu, s, off);
            q += __shfl_down_sync(0xffffffffu, q, off);
        }
        if (lane == 0) { red[wid][co] = s; red[wid][COUT + co] = q; }
    }
    __syncthreads();
    if (threadIdx.x < 2 * COUT) {
        float t = 0.f;
#pragma unroll
        for (int wdx = 0; wdx < 8; wdx++) t += red[wdx][threadIdx.x];
        g_part[blockIdx.x * 64 + threadIdx.x] = t;
    }
}

// ---------------- reduce partials, fold BN into per-channel scale/shift ----------------
__global__ void k_finalize(const float* __restrict__ gamma, const float* __restrict__ beta,
                           int cout)
{
    int c = threadIdx.x;   // blockDim = 64
    __shared__ float sums[64];
    double a = 0.0;
    for (int blk = 0; blk < NBLK; blk++) a += (double)g_part[blk * 64 + c];
    sums[c] = (float)a;
    __syncthreads();
    if (c < cout) {
        float m = sums[c] / (float)NPTS;
        float v = sums[cout + c] / (float)NPTS - m * m;
        float sc = gamma[c] * rsqrtf(v + EPSV);
        g_bn[c] = sc;
        g_bn[32 + c] = beta[c] - m * sc;
    }
}

// ---------------- BN3+ReLU fused segment-max pool ----------------
__global__ void k_pool(const int* __restrict__ idx) {
    int bb = blockIdx.y;
    int l = blockIdx.x * 256 + threadIdx.x;
    float v[32];
#pragma unroll
    for (int c = 0; c < 32; c++) v[c] = 0.f;
    int myb = -1;
    if (l < NPB) {
        int i = bb * NPB + l;
        myb = idx[3 * i];
        const float4* r = reinterpret_cast<const float4*>(g_y3 + (size_t)i * 32);
#pragma unroll
        for (int c4 = 0; c4 < 8; c4++) {
            float4 t = r[c4];
            float tv[4] = {t.x, t.y, t.z, t.w};
#pragma unroll
            for (int u = 0; u < 4; u++) {
                int c = c4 * 4 + u;
                v[c] = fmaxf(fmaf(tv[u], g_bn[c], g_bn[32 + c]), 0.f);
            }
        }
    }
    if (myb >= 0 && myb != bb) {
        // defensive fallback: point not batch-contiguous (not expected with this dataset)
#pragma unroll
        for (int c = 0; c < 32; c++) atomicMax(&g_pool[myb * 32 + c], __float_as_uint(v[c]));
#pragma unroll
        for (int c = 0; c < 32; c++) v[c] = 0.f;
    }
    __shared__ float red[8][32];
    int lane = threadIdx.x & 31, wid = threadIdx.x >> 5;
#pragma unroll
    for (int c = 0; c < 32; c++) {
        float m = v[c];
#pragma unroll
        for (int off = 16; off; off >>= 1)
            m = fmaxf(m, __shfl_down_sync(0xffffffffu, m, off));
        if (lane == 0) red[wid][c] = m;
    }
    __syncthreads();
    if (threadIdx.x < 32) {
        float m = 0.f;
#pragma unroll
        for (int wdx = 0; wdx < 8; wdx++) m = fmaxf(m, red[wdx][threadIdx.x]);
        atomicMax(&g_pool[bb * 32 + threadIdx.x], __float_as_uint(m));
    }
}

// ---------------- final FC + ReLU ----------------
__global__ void k_fc(const float* __restrict__ Wfc, const float* __restrict__ bfc,
                     float* __restrict__ out)
{
    int bb = blockIdx.x, co = threadIdx.x;   // 16 blocks x 128 threads
    __shared__ float p[32];
    if (threadIdx.x < 32) p[threadIdx.x] = __uint_as_float(g_pool[bb * 32 + threadIdx.x]);
    __syncthreads();
    float acc = bfc[co];
#pragma unroll
    for (int ci = 0; ci < 32; ci++)
        acc = fmaf(p[ci], Wfc[ci * 128 + co], acc);
    out[bb * 128 + co] = fmaxf(acc, 0.f);
}

// ---------------- launch ----------------
extern "C" void kernel_launch(void* const* d_in, const int* in_sizes, int n_in,
                              void* d_out, int out_size)
{
    const float* feats = (const float*)d_in[0];
    const int*   idx   = (const int*)d_in[1];
    const float* W1    = (const float*)d_in[2];
    const float* g1    = (const float*)d_in[3];
    const float* b1    = (const float*)d_in[4];
    const float* W2    = (const float*)d_in[5];
    const float* g2    = (const float*)d_in[6];
    const float* b2    = (const float*)d_in[7];
    const float* W3    = (const float*)d_in[8];
    const float* g3    = (const float*)d_in[9];
    const float* b3    = (const float*)d_in[10];
    const float* Wfc   = (const float*)d_in[11];
    const float* bfc   = (const float*)d_in[12];
    float* out = (float*)d_out;

    float *y1, *y2, *y3;
    cudaGetSymbolAddress((void**)&y1, g_y1);
    cudaGetSymbolAddress((void**)&y2, g_y2);
    cudaGetSymbolAddress((void**)&y3, g_y3);

    k_init<<<2048, 256>>>();
    k_scatter<<<NBLK, 256>>>(idx);

    k_conv<1, 8, false><<<NBLK, 256>>>(feats, idx, W1, y1);
    k_finalize<<<1, 64>>>(g1, b1, 8);

    k_conv<8, 16, true><<<NBLK, 256>>>(y1, idx, W2, y2);
    k_finalize<<<1, 64>>>(g2, b2, 16);

    k_conv<16, 32, true><<<NBLK, 256>>>(y2, idx, W3, y3);
    k_finalize<<<1, 64>>>(g3, b3, 32);

    dim3 pg((NPB + 255) / 256, NB);
    k_pool<<<pg, 256>>>(idx);
    k_fc<<<NB, 128>>>(Wfc, bfc, out);
}

// round 2
// speedup vs baseline: 1.2553x; 1.2553x over previous
#include <cuda_runtime.h>
#include <cstddef>

#define NB   16
#define HH   512
#define WWID 512
#define NPB  20000
#define NPTS (NB * NPB)        // 320000
#define EPSV 1e-5f
#define NBLK 1250              // NPTS / 256 exactly

// ---------------- scratch (device globals; no allocation allowed) ----------------
__device__ int g_map[NB * HH * WWID];                       // 16.8 MB dense index map
__device__ __align__(16) float g_y1[NPTS * 8];              // conv1 out (pre-BN)
__device__ __align__(16) float g_y2[NPTS * 16];             // conv2 out (pre-BN)
__device__ __align__(16) float g_y3[NPTS * 32];             // conv3 out (pre-BN)
__device__ float g_part[NBLK * 64];                         // per-block [sum|sumsq] partials
__device__ float g_bn[64];                                  // current layer: a[0..31], b[32..63]
__device__ unsigned g_pool[NB * 32];                        // segment max (uint bits of relu'd f32)

// ---------------- init: map = -1, pool = 0 (vectorized) ----------------
__global__ void k_init() {
    int i = blockIdx.x * blockDim.x + threadIdx.x;
    int stride = gridDim.x * blockDim.x;
    int4* m4 = reinterpret_cast<int4*>(g_map);
    const int n4 = NB * HH * WWID / 4;
    int4 neg = make_int4(-1, -1, -1, -1);
    for (int t = i; t < n4; t += stride) m4[t] = neg;
    if (i < NB * 32) g_pool[i] = 0u;
}

// ---------------- scatter point index into dense map ----------------
__global__ void k_scatter(const int* __restrict__ idx) {
    int i = blockIdx.x * blockDim.x + threadIdx.x;
    if (i < NPTS) {
        int b = idx[3 * i], y = idx[3 * i + 1], x = idx[3 * i + 2];
        g_map[(b << 18) | (y << 9) | x] = i;
    }
}

// ---------------- submanifold conv + fused input-BN-ReLU + stats partials ----------------
template <int CIN, int COUT, bool BN>
__global__ __launch_bounds__(256)
void k_conv(const float* __restrict__ in, const int* __restrict__ idx,
            const float* __restrict__ w, float* __restrict__ out)
{
    __shared__ float ws[9 * CIN * COUT];
    __shared__ float s_ab[BN ? 2 * CIN : 2];
    for (int t = threadIdx.x; t < 9 * CIN * COUT; t += 256) ws[t] = w[t];
    if (BN) {
        for (int t = threadIdx.x; t < 2 * CIN; t += 256)
            s_ab[t] = (t < CIN) ? g_bn[t] : g_bn[32 + (t - CIN)];
    }
    __syncthreads();

    int i = blockIdx.x * 256 + threadIdx.x;      // grid exact: NBLK*256 == NPTS
    float acc[COUT];
#pragma unroll
    for (int c = 0; c < COUT; c++) acc[c] = 0.f;

    int b = idx[3 * i], y = idx[3 * i + 1], x = idx[3 * i + 2];
    int base = b << 18;

#pragma unroll 1
    for (int ky = 0; ky < 3; ky++) {
        int ny = y + ky - 1;
        if ((unsigned)ny >= (unsigned)HH) continue;
#pragma unroll 1
        for (int kx = 0; kx < 3; kx++) {
            int nx = x + kx - 1;
            if ((unsigned)nx >= (unsigned)WWID) continue;
            int j = g_map[base + (ny << 9) + nx];
            if (j < 0) continue;
            const float* wr = &ws[(ky * 3 + kx) * (CIN * COUT)];
            const float* inr = in + (size_t)j * CIN;
            if (CIN >= 4) {
#pragma unroll
                for (int c4 = 0; c4 < CIN / 4; c4++) {
                    float4 v4 = reinterpret_cast<const float4*>(inr)[c4];
                    float vv[4] = {v4.x, v4.y, v4.z, v4.w};
#pragma unroll
                    for (int u = 0; u < 4; u++) {
                        int ci = c4 * 4 + u;
                        float v = vv[u];
                        if (BN) v = fmaxf(fmaf(v, s_ab[ci], s_ab[CIN + ci]), 0.f);
#pragma unroll
                        for (int co = 0; co < COUT; co++)
                            acc[co] = fmaf(v, wr[ci * COUT + co], acc[co]);
                    }
                }
            } else {
                float v = inr[0];
                if (BN) v = fmaxf(fmaf(v, s_ab[0], s_ab[CIN]), 0.f);
#pragma unroll
                for (int co = 0; co < COUT; co++)
                    acc[co] = fmaf(v, wr[co], acc[co]);
            }
        }
    }

    float4* orow = reinterpret_cast<float4*>(out + (size_t)i * COUT);
#pragma unroll
    for (int c4 = 0; c4 < COUT / 4; c4++) {
        float4 o;
        o.x = acc[4 * c4 + 0]; o.y = acc[4 * c4 + 1];
        o.z = acc[4 * c4 + 2]; o.w = acc[4 * c4 + 3];
        orow[c4] = o;
    }

    // block-level sum/sumsq partials (deterministic; no atomics)
    int lane = threadIdx.x & 31, wid = threadIdx.x >> 5;
    __shared__ float red[8][64];
#pragma unroll
    for (int co = 0; co < COUT; co++) {
        float s = acc[co];
        float q = acc[co] * acc[co];
#pragma unroll
        for (int off = 16; off; off >>= 1) {
            s += __shfl_down_sync(0xffffffffu, s, off);
            q += __shfl_down_sync(0xffffffffu, q, off);
        }
        if (lane == 0) { red[wid][co] = s; red[wid][COUT + co] = q; }
    }
    __syncthreads();
    if (threadIdx.x < 2 * COUT) {
        float t = 0.f;
#pragma unroll
        for (int wdx = 0; wdx < 8; wdx++) t += red[wdx][threadIdx.x];
        g_part[blockIdx.x * 64 + threadIdx.x] = t;
    }
}

// ---------------- PARALLEL reduce of partials, fold BN into per-channel scale/shift ----
// 1024 threads: thread t handles channel c = t&63, segment seg = t>>6 (16 segments).
// Each thread sums ~NBLK/16 independent L2-resident loads (full MLP), then a
// shared-memory tree combines the 16 segments per channel. Deterministic.
__global__ __launch_bounds__(1024)
void k_finalize(const float* __restrict__ gamma, const float* __restrict__ beta,
                int cout)
{
    int c = threadIdx.x & 63;
    int seg = threadIdx.x >> 6;          // 0..15
    float a = 0.f;
    for (int blk = seg; blk < NBLK; blk += 16)
        a += g_part[blk * 64 + c];

    __shared__ float s[16][64 + 1];      // +1 pad: conflict-free column reads
    s[seg][c] = a;
    __syncthreads();

    if (threadIdx.x < 64) {
        float t = 0.f;
#pragma unroll
        for (int k = 0; k < 16; k++) t += s[k][threadIdx.x];
        s[0][threadIdx.x] = t;
    }
    __syncthreads();
    if (threadIdx.x < (unsigned)cout) {
        float m = s[0][threadIdx.x] / (float)NPTS;
        float v = s[0][cout + threadIdx.x] / (float)NPTS - m * m;
        float sc = gamma[threadIdx.x] * rsqrtf(v + EPSV);
        g_bn[threadIdx.x] = sc;
        g_bn[32 + threadIdx.x] = beta[threadIdx.x] - m * sc;
    }
}

// ---------------- BN3+ReLU fused segment-max pool ----------------
__global__ void k_pool(const int* __restrict__ idx) {
    int bb = blockIdx.y;
    int l = blockIdx.x * 256 + threadIdx.x;
    float v[32];
#pragma unroll
    for (int c = 0; c < 32; c++) v[c] = 0.f;
    int myb = -1;
    if (l < NPB) {
        int i = bb * NPB + l;
        myb = idx[3 * i];
        const float4* r = reinterpret_cast<const float4*>(g_y3 + (size_t)i * 32);
#pragma unroll
        for (int c4 = 0; c4 < 8; c4++) {
            float4 t = r[c4];
            float tv[4] = {t.x, t.y, t.z, t.w};
#pragma unroll
            for (int u = 0; u < 4; u++) {
                int c = c4 * 4 + u;
                v[c] = fmaxf(fmaf(tv[u], g_bn[c], g_bn[32 + c]), 0.f);
            }
        }
    }
    if (myb >= 0 && myb != bb) {
#pragma unroll
        for (int c = 0; c < 32; c++) atomicMax(&g_pool[myb * 32 + c], __float_as_uint(v[c]));
#pragma unroll
        for (int c = 0; c < 32; c++) v[c] = 0.f;
    }
    __shared__ float red[8][32];
    int lane = threadIdx.x & 31, wid = threadIdx.x >> 5;
#pragma unroll
    for (int c = 0; c < 32; c++) {
        float m = v[c];
#pragma unroll
        for (int off = 16; off; off >>= 1)
            m = fmaxf(m, __shfl_down_sync(0xffffffffu, m, off));
        if (lane == 0) red[wid][c] = m;
    }
    __syncthreads();
    if (threadIdx.x < 32) {
        float m = 0.f;
#pragma unroll
        for (int wdx = 0; wdx < 8; wdx++) m = fmaxf(m, red[wdx][threadIdx.x]);
        atomicMax(&g_pool[bb * 32 + threadIdx.x], __float_as_uint(m));
    }
}

// ---------------- final FC + ReLU ----------------
__global__ void k_fc(const float* __restrict__ Wfc, const float* __restrict__ bfc,
                     float* __restrict__ out)
{
    int bb = blockIdx.x, co = threadIdx.x;   // 16 blocks x 128 threads
    __shared__ float p[32];
    if (threadIdx.x < 32) p[threadIdx.x] = __uint_as_float(g_pool[bb * 32 + threadIdx.x]);
    __syncthreads();
    float acc = bfc[co];
#pragma unroll
    for (int ci = 0; ci < 32; ci++)
        acc = fmaf(p[ci], Wfc[ci * 128 + co], acc);
    out[bb * 128 + co] = fmaxf(acc, 0.f);
}

// ---------------- launch ----------------
extern "C" void kernel_launch(void* const* d_in, const int* in_sizes, int n_in,
                              void* d_out, int out_size)
{
    const float* feats = (const float*)d_in[0];
    const int*   idx   = (const int*)d_in[1];
    const float* W1    = (const float*)d_in[2];
    const float* g1    = (const float*)d_in[3];
    const float* b1    = (const float*)d_in[4];
    const float* W2    = (const float*)d_in[5];
    const float* g2    = (const float*)d_in[6];
    const float* b2    = (const float*)d_in[7];
    const float* W3    = (const float*)d_in[8];
    const float* g3    = (const float*)d_in[9];
    const float* b3    = (const float*)d_in[10];
    const float* Wfc   = (const float*)d_in[11];
    const float* bfc   = (const float*)d_in[12];
    float* out = (float*)d_out;

    float *y1, *y2, *y3;
    cudaGetSymbolAddress((void**)&y1, g_y1);
    cudaGetSymbolAddress((void**)&y2, g_y2);
    cudaGetSymbolAddress((void**)&y3, g_y3);

    k_init<<<1024, 256>>>();
    k_scatter<<<NBLK, 256>>>(idx);

    k_conv<1, 8, false><<<NBLK, 256>>>(feats, idx, W1, y1);
    k_finalize<<<1, 1024>>>(g1, b1, 8);

    k_conv<8, 16, true><<<NBLK, 256>>>(y1, idx, W2, y2);
    k_finalize<<<1, 1024>>>(g2, b2, 16);

    k_conv<16, 32, true><<<NBLK, 256>>>(y2, idx, W3, y3);
    k_finalize<<<1, 1024>>>(g3, b3, 32);

    dim3 pg((NPB + 255) / 256, NB);
    k_pool<<<pg, 256>>>(idx);
    k_fc<<<NB, 128>>>(Wfc, bfc, out);
}